// round 17
// baseline (speedup 1.0000x reference)
#include <cuda_runtime.h>
#include <math.h>

#define Bn   2048
#define Hn   64
#define An   32
#define Sn   32
#define Dn   200
#define OUTC 296
#define BT   16
#define NT   1024

#define SZ   640   // [64][640]:  ru_z(416) | i_n(416..615) | pad
#define SH   640   // [208][640]: ru_h(416) | hn(416..615) | pad
#define S1   208

// ---------- persistent transposed weights ----------
__device__ float g_Wz [64  * SZ];
__device__ float g_Wfh[208 * SH];
__device__ float g_W1t[208 * S1];
__device__ float g_W2t[208 * S1];
__device__ float g_Wms[208 * 64];
__device__ float g_bru[416];
__device__ float g_bin[208];
__device__ float g_bhn[208];
__device__ float g_b1s[208];
__device__ float g_b2s[208];
__device__ float g_bms[64];

// ---------- packed fp32x2 helpers ----------
__device__ __forceinline__ unsigned long long fma2_(unsigned long long a,
                                                    unsigned long long b,
                                                    unsigned long long c) {
    unsigned long long d;
    asm("fma.rn.f32x2 %0, %1, %2, %3;" : "=l"(d) : "l"(a), "l"(b), "l"(c));
    return d;
}
__device__ __forceinline__ unsigned long long splat2_(float w) {
    unsigned long long d;
    asm("mov.b64 %0, {%1, %1};" : "=l"(d) : "f"(w));
    return d;
}
__device__ __forceinline__ void unpack2_(unsigned long long v, float& lo, float& hi) {
    asm("mov.b64 {%0, %1}, %2;" : "=f"(lo), "=f"(hi) : "l"(v));
}
__device__ __forceinline__ float sigf_(float x) { return 1.0f / (1.0f + __expf(-x)); }
#define YBAR() asm volatile("bar.sync 1, 384;" ::: "memory")

// ---------- weight transpose / fuse ----------
__global__ void rssm_preproc(
    const float* __restrict__ W_ih, const float* __restrict__ b_ih,
    const float* __restrict__ W_hh, const float* __restrict__ b_hh,
    const float* __restrict__ W1,   const float* __restrict__ b1,
    const float* __restrict__ W2,   const float* __restrict__ b2,
    const float* __restrict__ Wm,   const float* __restrict__ bm,
    const float* __restrict__ Ws,   const float* __restrict__ bs)
{
    int i0 = blockIdx.x * blockDim.x + threadIdx.x;
    int stride = gridDim.x * blockDim.x;

    for (int idx = i0; idx < 64 * SZ; idx += stride) {
        int k = idx / SZ, o = idx % SZ;
        float v = 0.0f;
        if (o < 400) v = W_ih[o * 64 + k];
        else if (o >= 416 && o < 616) v = W_ih[(400 + o - 416) * 64 + k];
        g_Wz[idx] = v;
    }
    for (int idx = i0; idx < 208 * SH; idx += stride) {
        int k = idx / SH, o = idx % SH;
        float v = 0.0f;
        if (k < 200) {
            if (o < 400) v = W_hh[o * 200 + k];
            else if (o >= 416 && o < 616) v = W_hh[(400 + o - 416) * 200 + k];
        }
        g_Wfh[idx] = v;
    }
    for (int idx = i0; idx < 208 * S1; idx += stride) {
        int k = idx / S1, o = idx % S1;
        bool live = (k < 200) && (o < 200);
        g_W1t[idx] = live ? W1[o * 200 + k] : 0.0f;
        g_W2t[idx] = live ? W2[o * 200 + k] : 0.0f;
    }
    for (int idx = i0; idx < 208 * 64; idx += stride) {
        int k = idx / 64, o = idx % 64;
        float v = 0.0f;
        if (k < 200) v = (o < 32) ? Wm[o * 200 + k] : Ws[(o - 32) * 200 + k];
        g_Wms[idx] = v;
    }
    for (int idx = i0; idx < 416; idx += stride)
        g_bru[idx] = (idx < 400) ? (b_ih[idx] + b_hh[idx]) : 0.0f;
    for (int idx = i0; idx < 208; idx += stride) {
        bool live = (idx < 200);
        g_bin[idx] = live ? b_ih[400 + idx] : 0.0f;
        g_bhn[idx] = live ? b_hh[400 + idx] : 0.0f;
        g_b1s[idx] = live ? b1[idx] : 0.0f;
        g_b2s[idx] = live ? b2[idx] : 0.0f;
    }
    for (int idx = i0; idx < 64; idx += stride)
        g_bms[idx] = (idx < 32) ? bm[idx] : bs[idx - 32];
}

// ---------- gemm2: C=2 cols x 8 rows (RG=2), LDG.64 weights, depth-4 prefetch ----
// threads used: NOUT. K % 8 == 0. Reg-lean (<=64 regs at NT=1024).
// BIAS: 0/1. ACT: 0=none, 2=elu.
template<int K, int SR, int BIAS, int ACT>
__device__ __forceinline__ void gemm2(const float* __restrict__ Wt,
                                      const float* __restrict__ bias,
                                      const float* __restrict__ xT,
                                      float* __restrict__ outT, int t)
{
    const int cg = t >> 1, rg = t & 1;
    const float* wp = Wt + cg * 2;
    const float* xb = xT + rg * 8;

    unsigned long long acc[2][4];
#pragma unroll
    for (int ci = 0; ci < 2; ci++)
#pragma unroll
        for (int q = 0; q < 4; q++) acc[ci][q] = 0ull;

    auto LD = [&](float2* b, int k0) {
#pragma unroll
        for (int p = 0; p < 4; p++)
            b[p] = __ldg(reinterpret_cast<const float2*>(wp + (size_t)(k0 + p) * SR));
    };
    auto CP = [&](const float2* b, int k0) {
#pragma unroll
        for (int p = 0; p < 4; p++) {
            int k = k0 + p;
            ulonglong2 xa = *reinterpret_cast<const ulonglong2*>(xb + k * BT);
            ulonglong2 xc = *reinterpret_cast<const ulonglong2*>(xb + k * BT + 4);
            unsigned long long w0 = splat2_(b[p].x), w1 = splat2_(b[p].y);
            acc[0][0] = fma2_(w0, xa.x, acc[0][0]);
            acc[0][1] = fma2_(w0, xa.y, acc[0][1]);
            acc[0][2] = fma2_(w0, xc.x, acc[0][2]);
            acc[0][3] = fma2_(w0, xc.y, acc[0][3]);
            acc[1][0] = fma2_(w1, xa.x, acc[1][0]);
            acc[1][1] = fma2_(w1, xa.y, acc[1][1]);
            acc[1][2] = fma2_(w1, xc.x, acc[1][2]);
            acc[1][3] = fma2_(w1, xc.y, acc[1][3]);
        }
    };

    float2 bufA[4], bufB[4];
    LD(bufA, 0);
    for (int k0 = 0; k0 < K; k0 += 8) {
        LD(bufB, k0 + 4);
        CP(bufA, k0);
        if (k0 + 8 < K) LD(bufA, k0 + 8);
        CP(bufB, k0 + 4);
    }

#pragma unroll
    for (int ci = 0; ci < 2; ci++) {
        int c = cg * 2 + ci;
        float bv = BIAS ? bias[c] : 0.0f;
        float v[8];
#pragma unroll
        for (int q = 0; q < 4; q++) {
            unpack2_(acc[ci][q], v[2 * q], v[2 * q + 1]);
            v[2 * q] += bv; v[2 * q + 1] += bv;
        }
        if (ACT == 2) {
#pragma unroll
            for (int r = 0; r < 8; r++) v[r] = v[r] > 0.0f ? v[r] : (__expf(v[r]) - 1.0f);
        }
        float* op = outT + c * BT + rg * 8;
        reinterpret_cast<float4*>(op)[0] = make_float4(v[0], v[1], v[2], v[3]);
        reinterpret_cast<float4*>(op)[1] = make_float4(v[4], v[5], v[6], v[7]);
    }
}

// ---------- main rollout kernel: 1 CTA = 16 rows, NT=1024, occ 50% ----------
extern __shared__ float smf[];

#define OXH  0                    // [272][16]: z 0..31, a 32..63, h 64..271 (pad 264..271)
#define OEP  (OXH + 272*16)       // [32][16] eps
#define OGZ  (OEP + 32*16)        // [640][16]: ru_z(416) | i_n(416..615)
#define OFH  (OGZ + 640*16)       // [640][16]: ru_h(416) | hn(416..615)
#define OF1  (OFH + 640*16)       // [208][16]
#define OF2  (OF1 + 208*16)       // [208][16]
#define OHP  (OF2 + 208*16)       // [6][64][16] head partials
#define OMS  (OHP + 6*64*16)      // [64][16] mean/std
#define SMEMF (OMS + 64*16)
#define SMEMB (SMEMF * 4)

__global__ void __launch_bounds__(NT, 1) rssm_main(
    const float* __restrict__ h0, const float* __restrict__ z0,
    const float* __restrict__ actions, const float* __restrict__ eps,
    float* __restrict__ out)
{
    float* xh  = smf + OXH;
    float* ep  = smf + OEP;
    float* gz  = smf + OGZ;
    float* fh  = smf + OFH;
    float* f1  = smf + OF1;
    float* f2  = smf + OF2;
    float* hp  = smf + OHP;
    float* ms  = smf + OMS;

    const int tid = threadIdx.x;
    const int b0  = blockIdx.x * BT;
    float* xhH = xh + 64 * BT;

    auto emit_step = [&](int tq, int i0, int istep) {
        for (int idx = i0; idx < OUTC * BT; idx += istep) {
            int r = idx / OUTC, c = idx - r * OUTC;
            float v;
            if (c < 200)      v = xhH[c * BT + r];
            else if (c < 232) v = xh[(c - 200) * BT + r];
            else              v = ms[(c - 232) * BT + r];
            out[((size_t)(b0 + r) * Hn + tq) * OUTC + c] = v;
        }
    };
    auto stage = [&](int tq, int i0, int istep) {
        for (int idx = i0; idx < An * BT; idx += istep) {
            int r = idx >> 5, c = idx & 31;
            size_t gbase = ((size_t)(b0 + r) * Hn + tq);
            xh[(32 + c) * BT + r] = actions[gbase * An + c];
            ep[c * BT + r]        = eps[gbase * Sn + c];
        }
    };

    // ---- prologue: state, pads, stage(0) ----
    for (int idx = tid; idx < Dn * BT; idx += NT) {
        int f = idx >> 4, r = idx & 15;
        xhH[idx] = h0[(b0 + r) * Dn + f];
    }
    for (int idx = tid; idx < Sn * BT; idx += NT) {
        int f = idx >> 4, r = idx & 15;
        xh[idx] = z0[(b0 + r) * Sn + f];
    }
    for (int idx = tid; idx < 8 * BT; idx += NT) {
        xhH[200 * BT + idx] = 0.0f;
        f1[200 * BT + idx] = 0.0f;
        f2[200 * BT + idx] = 0.0f;
    }
    stage(0, tid, NT);
    __syncthreads();

    // prologue fused-h from h0 (640 cols incl zero-pad)
    if (tid < 640)
        gemm2<208, SH, 0, 0>(g_Wfh, nullptr, xhH, fh, tid);
    __syncthreads();

    for (int t = 0; t < Hn; t++) {
        // ---- P1: fused z-GEMM on warps 0-19; emit(t-1) on warps 20-31 ----
        if (tid < 640) {
            gemm2<64, SZ, 0, 0>(g_Wz, nullptr, xh, gz, tid);
        } else if (t > 0) {
            emit_step(t - 1, tid - 640, NT - 640);
        }
        __syncthreads();

        // ---- P2: pointwise GRU update (all 1024 threads) ----
        for (int idx = tid; idx < Dn * BT; idx += NT) {
            int f = idx >> 4, r = idx & 15;
            float rr = sigf_(gz[idx] + fh[idx] + g_bru[f]);
            float uu = sigf_(gz[(200 + f) * BT + r] + fh[(200 + f) * BT + r] + g_bru[200 + f]);
            float hn = fh[(416 + f) * BT + r] + g_bhn[f];
            float nn = tanhf(gz[(416 + f) * BT + r] + g_bin[f] + rr * hn);
            float hv = xhH[idx];
            xhH[idx] = (1.0f - uu) * nn + uu * hv;
        }
        __syncthreads();

        // ---- P3: X (warps 0-19) next-step fused-h; Y (warps 20-31) MLP chain ----
        if (tid < 640) {
            gemm2<208, SH, 0, 0>(g_Wfh, nullptr, xhH, fh, tid);
        } else {
            int ty = tid - 640;   // 0..383 (12 warps)
            if (ty < 208)
                gemm2<208, S1, 1, 2>(g_W1t, g_b1s, xhH, f1, ty);   // f1 = elu
            YBAR();
            if (ty < 208)
                gemm2<208, S1, 1, 2>(g_W2t, g_b2s, f1, f2, ty);    // f2 = elu
            YBAR();
            {
                // heads: 6-way K-split {35,35,35,35,34,34}, 384 threads
                int p = ty >> 6, o = ty & 63;
                int k0 = p * 35;
                int kn = (p < 4) ? 35 : 34;
                if (p == 5) k0 = 174;
                const float* wp = g_Wms + k0 * 64 + o;
                const float* xb = f2 + k0 * BT;
                unsigned long long acc[8];
#pragma unroll
                for (int q = 0; q < 8; q++) acc[q] = 0ull;
                for (int k = 0; k < kn; k++) {
                    float w0 = __ldg(wp + k * 64);
                    unsigned long long wd0 = splat2_(w0);
                    const ulonglong2* x0 = reinterpret_cast<const ulonglong2*>(xb + k * BT);
#pragma unroll
                    for (int q = 0; q < 4; q++) {
                        ulonglong2 a = x0[q];
                        acc[2 * q]     = fma2_(wd0, a.x, acc[2 * q]);
                        acc[2 * q + 1] = fma2_(wd0, a.y, acc[2 * q + 1]);
                    }
                }
                float v[16];
#pragma unroll
                for (int q = 0; q < 8; q++) { unpack2_(acc[q], v[2 * q], v[2 * q + 1]); }
                float4* dp = reinterpret_cast<float4*>(hp + p * 1024 + o * BT);
#pragma unroll
                for (int q = 0; q < 4; q++)
                    dp[q] = make_float4(v[4 * q], v[4 * q + 1], v[4 * q + 2], v[4 * q + 3]);
            }
            YBAR();
            for (int idx = ty; idx < 1024; idx += 384) {
                int o = idx >> 4;
                float v = g_bms[o];
#pragma unroll
                for (int p = 0; p < 6; p++) v += hp[p * 1024 + idx];
                if (o < 32) ms[idx] = v;
                else        ms[idx] = __expf(fminf(fmaxf(v, -10.0f), 2.0f));
            }
            YBAR();
            for (int idx = ty; idx < Sn * BT; idx += 384)
                xh[idx] = ms[idx] + ms[512 + idx] * ep[idx];
        }
        __syncthreads();   // join

        // ---- P4: stage t+1 (all threads; 512 elems) ----
        if (t + 1 < Hn) stage(t + 1, tid, NT);
        __syncthreads();
    }

    emit_step(Hn - 1, tid, NT);
}

// ---------- launch ----------
extern "C" void kernel_launch(void* const* d_in, const int* in_sizes, int n_in,
                              void* d_out, int out_size)
{
    const float* h0      = (const float*)d_in[0];
    const float* z0      = (const float*)d_in[1];
    const float* actions = (const float*)d_in[2];
    const float* eps_    = (const float*)d_in[3];
    const float* W_ih = (const float*)d_in[4];  const float* b_ih = (const float*)d_in[5];
    const float* W_hh = (const float*)d_in[6];  const float* b_hh = (const float*)d_in[7];
    const float* W1   = (const float*)d_in[8];  const float* b1   = (const float*)d_in[9];
    const float* W2   = (const float*)d_in[10]; const float* b2   = (const float*)d_in[11];
    const float* Wm   = (const float*)d_in[12]; const float* bm   = (const float*)d_in[13];
    const float* Ws   = (const float*)d_in[14]; const float* bs   = (const float*)d_in[15];
    float* out = (float*)d_out;

    cudaFuncSetAttribute(rssm_main, cudaFuncAttributeMaxDynamicSharedMemorySize, SMEMB);

    rssm_preproc<<<128, 256>>>(W_ih, b_ih, W_hh, b_hh, W1, b1, W2, b2, Wm, bm, Ws, bs);
    rssm_main<<<Bn / BT, NT, SMEMB>>>(h0, z0, actions, eps_, out);
}